// round 15
// baseline (speedup 1.0000x reference)
#include <cuda_runtime.h>
#include <cuda_fp16.h>
#include <cstdint>

#define B_DIM 64
#define S_DIM 2048
#define H_DIM 1024
#define E_DIM 2048               // K of the big GEMM
#define M_DIM (B_DIM * S_DIM)    // 131072
#define TM 128
#define TN 128
#define TK 64
#define NKT (E_DIM / TK)         // 32
#define NBLK (H_DIM / TN)        // 8 n-blocks
#define NCHUNK 8
#define MB_TOTAL (M_DIM / TM)    // 1024 m-tiles
#define MB_PER_CHUNK (MB_TOTAL / NCHUNK)     // 128

#define A_TILE_BYTES (TM * TK * 2)           // 16384
#define STAGE_BYTES (2 * A_TILE_BYTES)       // 32768 (A + B)
#define STAGES 3
#define SMEM_DYN (STAGES * STAGE_BYTES)      // 98304

// device scratch (no cudaMalloc allowed)
__device__ float g_decf[B_DIM * H_DIM];
__device__ float g_partial[(size_t)M_DIM * NBLK];
__device__ __half g_eo_h[(size_t)M_DIM * E_DIM];     // eo in half, row-major [m][k]
__device__ __half g_wst_h[(size_t)H_DIM * E_DIM];    // W_s^T in half, [n][k]

__device__ __forceinline__ uint32_t smem_u32(const void* p) {
    uint32_t a;
    asm("{ .reg .u64 t; cvta.to.shared.u64 t, %1; cvt.u32.u64 %0, t; }" : "=r"(a) : "l"(p));
    return a;
}
__device__ __forceinline__ float tanh_ap(float x) {
    float y;
    asm("tanh.approx.f32 %0, %1;" : "=f"(y) : "f"(x));
    return y;
}
__device__ __forceinline__ void cp16(uint32_t dst, const void* src) {
    asm volatile("cp.async.cg.shared.global [%0], [%1], 16;" :: "r"(dst), "l"(src));
}
__device__ __forceinline__ void cp_commit() { asm volatile("cp.async.commit_group;"); }
template <int N>
__device__ __forceinline__ void cp_wait() { asm volatile("cp.async.wait_group %0;" :: "n"(N)); }

__device__ __forceinline__ void ldm4(uint32_t& r0, uint32_t& r1, uint32_t& r2, uint32_t& r3,
                                     uint32_t addr) {
    asm volatile("ldmatrix.sync.aligned.m8n8.x4.shared.b16 {%0,%1,%2,%3}, [%4];"
                 : "=r"(r0), "=r"(r1), "=r"(r2), "=r"(r3) : "r"(addr));
}
__device__ __forceinline__ void mma16(float& c0, float& c1, float& c2, float& c3,
                                      uint32_t a0, uint32_t a1, uint32_t a2, uint32_t a3,
                                      uint32_t b0, uint32_t b1) {
    asm volatile(
        "mma.sync.aligned.m16n8k16.row.col.f32.f16.f16.f32 "
        "{%0,%1,%2,%3},{%4,%5,%6,%7},{%8,%9},{%0,%1,%2,%3};\n"
        : "+f"(c0), "+f"(c1), "+f"(c2), "+f"(c3)
        : "r"(a0), "r"(a1), "r"(a2), "r"(a3), "r"(b0), "r"(b1));
}

// ---------------------------------------------------------------------------
// Kernel 0a: eo (fp32) -> g_eo_h (fp16), chunked over M. 8 elems per thread.
// ---------------------------------------------------------------------------
__global__ __launch_bounds__(256) void cvt_eo(const float* __restrict__ eo,
                                              size_t g0) {
    const size_t g = g0 + (size_t)blockIdx.x * 256 + threadIdx.x;
    const float4* in = reinterpret_cast<const float4*>(eo) + g * 2;
    const float4 t0 = in[0], t1 = in[1];
    __half2 o[4];
    o[0] = __floats2half2_rn(t0.x, t0.y);
    o[1] = __floats2half2_rn(t0.z, t0.w);
    o[2] = __floats2half2_rn(t1.x, t1.y);
    o[3] = __floats2half2_rn(t1.z, t1.w);
    reinterpret_cast<uint4*>(g_eo_h)[g] = *reinterpret_cast<uint4*>(&o[0]);
}

// ---------------------------------------------------------------------------
// Kernel 0b: W_s [2048,1024] fp32 -> g_wst_h [1024][2048] fp16 (transpose)
// ---------------------------------------------------------------------------
__global__ __launch_bounds__(256) void cvt_ws(const float* __restrict__ Ws) {
    __shared__ float tile[32][33];
    const int tx = threadIdx.x & 31, ty = threadIdx.x >> 5;   // 32x8
    const int k0 = blockIdx.x * 32, n0 = blockIdx.y * 32;
#pragma unroll
    for (int j = 0; j < 4; j++)
        tile[ty + j * 8][tx] = Ws[(size_t)(k0 + ty + j * 8) * H_DIM + n0 + tx];
    __syncthreads();
#pragma unroll
    for (int j = 0; j < 4; j++)
        g_wst_h[(size_t)(n0 + ty + j * 8) * E_DIM + k0 + tx] =
            __float2half_rn(tile[tx][ty + j * 8]);
}

// ---------------------------------------------------------------------------
// Kernel 1: dec_f = decoder_hidden @ W_h, split over 4 column blocks
// ---------------------------------------------------------------------------
__global__ __launch_bounds__(256) void decf_kernel(const float* __restrict__ dh,
                                                   const float* __restrict__ Wh) {
    __shared__ float ds[H_DIM];
    const int b = blockIdx.x, q = blockIdx.y;
    for (int i = threadIdx.x; i < H_DIM; i += 256) ds[i] = dh[b * H_DIM + i];
    __syncthreads();
    const int n = q * 256 + threadIdx.x;
    float a0 = 0.f, a1 = 0.f, a2 = 0.f, a3 = 0.f;
#pragma unroll 4
    for (int h = 0; h < H_DIM; h += 4) {
        a0 += ds[h] * Wh[(size_t)h * H_DIM + n];
        a1 += ds[h + 1] * Wh[(size_t)(h + 1) * H_DIM + n];
        a2 += ds[h + 2] * Wh[(size_t)(h + 2) * H_DIM + n];
        a3 += ds[h + 3] * Wh[(size_t)(h + 3) * H_DIM + n];
    }
    g_decf[b * H_DIM + n] = (a0 + a1) + (a2 + a3);
}

// ---------------------------------------------------------------------------
// Kernel 2: fp16 mma GEMM (eo @ W_s) + tanh/v epilogue -> partial energies
// CTA 128x128x64, 3-stage cp.async, SW128-swizzled smem, ldmatrix fragments
// (GEMM body unchanged from round 10/13 — measured tensor=79.2%; now chunked)
// ---------------------------------------------------------------------------
extern __shared__ __align__(16) char dsmc[];

__global__ __launch_bounds__(256, 2) void energy_gemm(const float* __restrict__ v,
                                                      int mb0) {
    __shared__ float vs[TN], dfs[TN], esum[TM * 4];

    const int tid = threadIdx.x;
    const int nb = blockIdx.x;        // fastest -> A-tile L2 reuse across 8 nb
    const int mb = mb0 + blockIdx.y;
    const int m0 = mb << 7;
    const int n0 = nb << 7;
    const int b = mb >> 4;            // 16 m-tiles per batch row

    if (tid < 128) {
        vs[tid] = v[n0 + tid];
        dfs[tid] = g_decf[b * H_DIM + n0 + tid];
    }

    const uint32_t dynb = smem_u32(dsmc);
    const __half* Abase = g_eo_h + (size_t)m0 * E_DIM;
    const __half* Bbase = g_wst_h + (size_t)n0 * E_DIM;

    auto load_stage = [&](int n, int s) {
        const uint32_t base = dynb + (uint32_t)s * STAGE_BYTES;
        const uint32_t baseB = base + A_TILE_BYTES;
#pragma unroll
        for (int i = 0; i < 4; i++) {
            const int id = tid + i * 256;            // 0..1023
            const int row = id >> 3, c = id & 7;
            const uint32_t off = (uint32_t)(row * 128 + ((c * 16) ^ ((row & 7) << 4)));
            cp16(base + off, Abase + (size_t)row * E_DIM + n * TK + c * 8);
        }
#pragma unroll
        for (int i = 0; i < 4; i++) {
            const int id = tid + i * 256;
            const int row = id >> 3, c = id & 7;
            const uint32_t off = (uint32_t)(row * 128 + ((c * 16) ^ ((row & 7) << 4)));
            cp16(baseB + off, Bbase + (size_t)row * E_DIM + n * TK + c * 8);
        }
        cp_commit();
    };

    const int warp = tid >> 5, lane = tid & 31;
    const int gid = lane >> 2, tig = lane & 3;
    const int wm = (warp >> 2) << 6;   // 0 or 64
    const int wn = (warp & 3) << 5;    // 0,32,64,96

    const uint32_t a_row_off = (uint32_t)((wm + (lane & 15)) * 128);
    const uint32_t amix = (uint32_t)((((lane >> 4) & 1) * 16) ^ ((lane & 7) << 4));
    const uint32_t b_row_off = (uint32_t)((wn + ((lane >> 4) & 1) * 8 + (lane & 7)) * 128);
    const uint32_t bmix = (uint32_t)((((lane >> 3) & 1) * 16) ^ ((lane & 7) << 4));

    float acc[4][4][4];
#pragma unroll
    for (int i = 0; i < 4; i++)
#pragma unroll
        for (int j = 0; j < 4; j++)
#pragma unroll
            for (int k = 0; k < 4; k++) acc[i][j][k] = 0.f;

    load_stage(0, 0);
    load_stage(1, 1);

    for (int kt = 0; kt < NKT; kt++) {
        if (kt == NKT - 1) cp_wait<0>(); else cp_wait<1>();
        __syncthreads();

        if (kt + 2 < NKT) load_stage(kt + 2, (kt + 2) % 3);

        const uint32_t sA = dynb + (uint32_t)(kt % 3) * STAGE_BYTES;
        const uint32_t aB = sA + a_row_off;
        const uint32_t bB = sA + A_TILE_BYTES + b_row_off;

#pragma unroll
        for (int ks = 0; ks < 4; ks++) {
            const uint32_t kbs = (uint32_t)(ks * 32);
            const uint32_t ax = kbs ^ amix;
            const uint32_t bx = kbs ^ bmix;
            uint32_t a[4][4], bb[2][4];
#pragma unroll
            for (int mt = 0; mt < 4; mt++)
                ldm4(a[mt][0], a[mt][1], a[mt][2], a[mt][3], aB + mt * 2048 + ax);
#pragma unroll
            for (int p = 0; p < 2; p++)
                ldm4(bb[p][0], bb[p][1], bb[p][2], bb[p][3], bB + p * 2048 + bx);
#pragma unroll
            for (int mt = 0; mt < 4; mt++)
#pragma unroll
                for (int nt = 0; nt < 4; nt++) {
                    const uint32_t b0 = bb[nt >> 1][(nt & 1) * 2];
                    const uint32_t b1 = bb[nt >> 1][(nt & 1) * 2 + 1];
                    mma16(acc[mt][nt][0], acc[mt][nt][1], acc[mt][nt][2], acc[mt][nt][3],
                          a[mt][0], a[mt][1], a[mt][2], a[mt][3], b0, b1);
                }
        }
    }

    // Epilogue: partial energy = sum_n v[n] * tanh(dec_f[b,n] + c[m,n])
#pragma unroll
    for (int mt = 0; mt < 4; mt++) {
        float s0 = 0.f, s1 = 0.f;
#pragma unroll
        for (int nt = 0; nt < 4; nt++) {
            const int c = wn + nt * 8 + tig * 2;
            const float v0 = vs[c], v1 = vs[c + 1];
            const float d0 = dfs[c], d1 = dfs[c + 1];
            s0 += v0 * tanh_ap(d0 + acc[mt][nt][0]);
            s0 += v1 * tanh_ap(d1 + acc[mt][nt][1]);
            s1 += v0 * tanh_ap(d0 + acc[mt][nt][2]);
            s1 += v1 * tanh_ap(d1 + acc[mt][nt][3]);
        }
        s0 += __shfl_xor_sync(0xffffffffu, s0, 1);
        s0 += __shfl_xor_sync(0xffffffffu, s0, 2);
        s1 += __shfl_xor_sync(0xffffffffu, s1, 1);
        s1 += __shfl_xor_sync(0xffffffffu, s1, 2);
        if (tig == 0) {
            esum[(wm + mt * 16 + gid) * 4 + (warp & 3)] = s0;
            esum[(wm + mt * 16 + 8 + gid) * 4 + (warp & 3)] = s1;
        }
    }
    __syncthreads();
    if (tid < 128) {
        const float t = (esum[tid * 4] + esum[tid * 4 + 1]) + (esum[tid * 4 + 2] + esum[tid * 4 + 3]);
        g_partial[(size_t)(m0 + tid) * NBLK + nb] = t;
    }
}

// ---------------------------------------------------------------------------
// Kernel 3: per-batch masked softmax over S
// ---------------------------------------------------------------------------
__global__ __launch_bounds__(256) void softmax_kernel(const int* __restrict__ mask,
                                                      float* __restrict__ attn) {
    __shared__ float es[S_DIM];
    __shared__ float red[256];
    const int b = blockIdx.x, t = threadIdx.x;

    float lmax = -3.0e38f;
    for (int s = t; s < S_DIM; s += 256) {
        const float* p = &g_partial[(size_t)((b << 11) + s) * NBLK];
        float e = ((p[0] + p[1]) + (p[2] + p[3])) + ((p[4] + p[5]) + (p[6] + p[7]));
        if (mask[(b << 11) + s] == 0) e = -1e10f;
        es[s] = e;
        lmax = fmaxf(lmax, e);
    }
    red[t] = lmax;
    __syncthreads();
    for (int o = 128; o > 0; o >>= 1) {
        if (t < o) red[t] = fmaxf(red[t], red[t + o]);
        __syncthreads();
    }
    const float m = red[0];
    __syncthreads();

    float ls = 0.f;
    for (int s = t; s < S_DIM; s += 256) {
        const float x = __expf(es[s] - m);
        es[s] = x;
        ls += x;
    }
    red[t] = ls;
    __syncthreads();
    for (int o = 128; o > 0; o >>= 1) {
        if (t < o) red[t] += red[t + o];
        __syncthreads();
    }
    const float inv = 1.0f / red[0];
    for (int s = t; s < S_DIM; s += 256) attn[(b << 11) + s] = es[s] * inv;
}

// ---------------------------------------------------------------------------
// Kernel 4: context[b,e] = sum_s attn[b,s] * eo_h[b,s,e]  (fp16 read: 0.5GB)
// ---------------------------------------------------------------------------
__global__ __launch_bounds__(256) void context_kernel(const float* __restrict__ attn,
                                                      float* __restrict__ ctx) {
    __shared__ float as_[S_DIM];
    __shared__ float red[4][64][8];
    const int b = blockIdx.y, t = threadIdx.x;
    for (int s = t; s < S_DIM; s += 256) as_[s] = attn[(b << 11) + s];
    __syncthreads();

    const int lane = t & 63, stripe = t >> 6;
    const int e8 = blockIdx.x * 64 + lane;
    const uint4* p = reinterpret_cast<const uint4*>(g_eo_h + (size_t)b * S_DIM * E_DIM) + e8;
    float acc[8];
#pragma unroll
    for (int j = 0; j < 8; j++) acc[j] = 0.f;
    const int sbeg = stripe * 512;
#pragma unroll 4
    for (int i = 0; i < 512; i++) {
        const int s = sbeg + i;
        const float w = as_[s];
        const uint4 q = p[(size_t)s * 256];
        const __half2* h = reinterpret_cast<const __half2*>(&q);
#pragma unroll
        for (int j = 0; j < 4; j++) {
            const float2 f = __half22float2(h[j]);
            acc[2 * j] += w * f.x;
            acc[2 * j + 1] += w * f.y;
        }
    }
#pragma unroll
    for (int j = 0; j < 8; j++) red[stripe][lane][j] = acc[j];
    __syncthreads();
    if (t < 64) {
        float o[8];
#pragma unroll
        for (int j = 0; j < 8; j++)
            o[j] = (red[0][t][j] + red[1][t][j]) + (red[2][t][j] + red[3][t][j]);
        float4* dst = reinterpret_cast<float4*>(ctx + (size_t)b * E_DIM + blockIdx.x * 512 + t * 8);
        dst[0] = make_float4(o[0], o[1], o[2], o[3]);
        dst[1] = make_float4(o[4], o[5], o[6], o[7]);
    }
}

// ---------------------------------------------------------------------------
// Launch: chunked cvt_eo on the main stream, energy_gemm chunks forked onto a
// side stream gated by events -> conversion overlaps GEMM compute.
// Streams/events created once (infra; per-call captured work is identical).
// ---------------------------------------------------------------------------
extern "C" void kernel_launch(void* const* d_in, const int* in_sizes, int n_in,
                              void* d_out, int out_size) {
    const float* dh = (const float*)d_in[0];   // [64,1024]
    const float* eo = (const float*)d_in[1];   // [64,2048,2048]
    const int* mask = (const int*)d_in[2];     // [64,2048]
    const float* Wh = (const float*)d_in[3];   // [1024,1024]
    const float* Ws = (const float*)d_in[4];   // [2048,1024]
    const float* v = (const float*)d_in[5];    // [1024]

    float* out = (float*)d_out;
    float* out_ctx = out;                      // context [64,2048]
    float* out_attn = out + B_DIM * E_DIM;     // attn_weights [64,2048]

    static cudaStream_t s1 = nullptr;
    static cudaEvent_t ev[NCHUNK + 1];
    if (s1 == nullptr) {
        cudaStreamCreateWithFlags(&s1, cudaStreamNonBlocking);
        for (int i = 0; i <= NCHUNK; i++)
            cudaEventCreateWithFlags(&ev[i], cudaEventDisableTiming);
    }

    cudaFuncSetAttribute(energy_gemm, cudaFuncAttributeMaxDynamicSharedMemorySize, SMEM_DYN);

    // prerequisites for the GEMM (main stream, before first chunk event)
    cvt_ws<<<dim3(E_DIM / 32, H_DIM / 32), 256>>>(Ws);
    decf_kernel<<<dim3(B_DIM, 4), 256>>>(dh, Wh);

    const int cvt_blocks = (M_DIM / NCHUNK) * (E_DIM / 8) / 256;   // 8192 per chunk
    for (int c = 0; c < NCHUNK; c++) {
        cvt_eo<<<cvt_blocks, 256>>>(eo, (size_t)c * cvt_blocks * 256);
        cudaEventRecord(ev[c], 0);
        cudaStreamWaitEvent(s1, ev[c], 0);
        energy_gemm<<<dim3(NBLK, MB_PER_CHUNK), 256, SMEM_DYN, s1>>>(v, c * MB_PER_CHUNK);
    }
    cudaEventRecord(ev[NCHUNK], s1);
    cudaStreamWaitEvent(0, ev[NCHUNK], 0);     // join side stream back

    softmax_kernel<<<B_DIM, 256>>>(mask, out_attn);
    context_kernel<<<dim3(4, B_DIM), 256>>>(out_attn, out_ctx);
}